// round 4
// baseline (speedup 1.0000x reference)
#include <cuda_runtime.h>

// Problem dims
#define NB  16
#define CCH 256
#define TT  256
#define VV  25
#define VPN 20
#define SS  3
#define ICN 64
#define CT   (CCH*TT)      // 65536
#define NCOL (TT*VPN)      // 5120
#define M1 384             // fa|fb stacked rows
#define KK1 256
#define M2 256
#define KK2 768

// ---------------- scratch (device globals; no runtime allocation) -------------
__device__ float g_xp[(size_t)NB*CT*VPN];        // (N, C*T, VP)
__device__ float g_fab[(size_t)NB*M1*NCOL];      // (N, 384, 5120)
__device__ float g_spart[16*48*400];             // score partials per t-chunk
__device__ float g_att[48*400];                  // (N*S, VP, VP)
__device__ float g_z[(size_t)NB*SS*CT*VPN];      // (N,S,C*T,VP)
__device__ float g_y[(size_t)NB*CCH*NCOL];       // (N, C, T*VP)
__device__ float g_bn[2*CCH];                    // mean, rstd

// ---------------- packed fp32x2 helpers ----------------
typedef unsigned long long u64;
__device__ __forceinline__ void fma2(u64 &d, u64 a, u64 b){ asm("fma.rn.f32x2 %0, %1, %2, %0;" : "+l"(d) : "l"(a), "l"(b)); }
__device__ __forceinline__ float2 up2(u64 v){ float lo, hi; asm("mov.b64 {%0,%1}, %2;" : "=f"(lo), "=f"(hi) : "l"(v)); return make_float2(lo,hi); }

// ---------------- K1: xp = einsum('nctv,vu->nctu', x, w_e) + b_e --------------
__global__ void __launch_bounds__(256) k1_xp(const float* __restrict__ x,
                                             const float* __restrict__ w_e,
                                             const float* __restrict__ b_e) {
    __shared__ float sw[VV*VPN];
    __shared__ float sb[VPN];
    int tid = threadIdx.x;
    for (int i = tid; i < VV*VPN; i += 256) sw[i] = w_e[i];
    if (tid < VPN) sb[tid] = b_e[tid];
    __syncthreads();
    size_t row0 = ((size_t)blockIdx.x * 256 + tid) * 2;
    float xr[2][VV];
    #pragma unroll
    for (int r = 0; r < 2; r++) {
        const float* xr0 = x + (row0 + r) * VV;
        #pragma unroll
        for (int v = 0; v < VV; v++) xr[r][v] = xr0[v];
    }
    float acc[2][VPN];
    #pragma unroll
    for (int u = 0; u < VPN; u++) { float b = sb[u]; acc[0][u] = b; acc[1][u] = b; }
    #pragma unroll
    for (int v = 0; v < VV; v++) {
        float x0 = xr[0][v], x1 = xr[1][v];
        #pragma unroll
        for (int u = 0; u < VPN; u++) {
            float w = sw[v*VPN + u];
            acc[0][u] += x0 * w;
            acc[1][u] += x1 * w;
        }
    }
    #pragma unroll
    for (int r = 0; r < 2; r++) {
        float* o = &g_xp[(row0 + r) * VPN];
        #pragma unroll
        for (int q = 0; q < 5; q++)
            *(float4*)(o + q*4) = make_float4(acc[r][q*4], acc[r][q*4+1], acc[r][q*4+2], acc[r][q*4+3]);
    }
}

// ---------------- tiled batched GEMM (128x128x16, 8x8 micro, pure f32x2) ------
// A tile stored DUPLICATED in smem so LDS.128 yields packed (a,a) u64 operands:
// zero MOV packing in the inner loop. NO min-blocks bound -> no register spills.
// MODE 0: fa/fb  — A rows: [wa(192x256); wb(192x256)], B = xp[n], C = fab[n]
// MODE 1: y      — A[o][k=s*256+c] = wd[s,o,c],        B = z[n],  C = y[n]
template<int MODE>
__global__ void __launch_bounds__(256) gemm_k(const float* __restrict__ W0,
                                              const float* __restrict__ W1,
                                              const float* __restrict__ bias0,
                                              const float* __restrict__ bias1) {
    constexpr int MM = (MODE == 0) ? M1 : M2;
    constexpr int KD = (MODE == 0) ? KK1 : KK2;
    __shared__ float As2[16][264];   // duplicated A: As2[kk][2m]=As2[kk][2m+1]
    __shared__ float Bs[16][128];

    const float* B    = (MODE == 0) ? g_xp : g_z;
    float*       Cout = (MODE == 0) ? g_fab : g_y;

    int tid = threadIdx.x;
    int n   = blockIdx.z;
    const float* Bn = B    + (size_t)n * KD * NCOL;
    float*       Cn = Cout + (size_t)n * MM * NCOL;

    int row0 = blockIdx.y * 128;
    int col0 = blockIdx.x * 128;
    int tm = tid >> 4, tn = tid & 15;
    int ra = tid >> 2;            // 0..63
    int ka = (tid & 3) << 2;      // 0,4,8,12
    int colb = (tid & 31) << 2;   // 0..124
    int kb = tid >> 5;            // 0..7

    u64 acc[8][4];
    #pragma unroll
    for (int i = 0; i < 8; i++)
        #pragma unroll
        for (int j = 0; j < 4; j++) acc[i][j] = 0ull;

    auto a_ptr = [&](int r, int kg) -> const float* {
        if (MODE == 0) return (r < 192) ? (W0 + r*256 + kg) : (W1 + (r-192)*256 + kg);
        int s = kg >> 8, c = kg & 255;
        return W0 + s*65536 + r*256 + c;
    };

    // prefetch first k-tile into registers
    float4 avr[2], bvr[2];
    #pragma unroll
    for (int h = 0; h < 2; h++) {
        avr[h] = *(const float4*)a_ptr(row0 + ra + h*64, ka);
        bvr[h] = *(const float4*)&Bn[(size_t)(kb + h*8)*NCOL + col0 + colb];
    }

    for (int k0 = 0; k0 < KD; k0 += 16) {
        #pragma unroll
        for (int h = 0; h < 2; h++) {
            int m2 = 2*(ra + h*64);
            *(float2*)&As2[ka+0][m2] = make_float2(avr[h].x, avr[h].x);
            *(float2*)&As2[ka+1][m2] = make_float2(avr[h].y, avr[h].y);
            *(float2*)&As2[ka+2][m2] = make_float2(avr[h].z, avr[h].z);
            *(float2*)&As2[ka+3][m2] = make_float2(avr[h].w, avr[h].w);
            *(float4*)&Bs[kb + h*8][colb] = bvr[h];
        }
        __syncthreads();
        if (k0 + 16 < KD) {
            #pragma unroll
            for (int h = 0; h < 2; h++) {
                avr[h] = *(const float4*)a_ptr(row0 + ra + h*64, k0 + 16 + ka);
                bvr[h] = *(const float4*)&Bn[(size_t)(k0 + 16 + kb + h*8)*NCOL + col0 + colb];
            }
        }
        #pragma unroll
        for (int kk = 0; kk < 16; kk++) {
            ulonglong2 A0 = *(const ulonglong2*)&As2[kk][16*tm];
            ulonglong2 A1 = *(const ulonglong2*)&As2[kk][16*tm + 4];
            ulonglong2 A2 = *(const ulonglong2*)&As2[kk][16*tm + 8];
            ulonglong2 A3 = *(const ulonglong2*)&As2[kk][16*tm + 12];
            ulonglong2 B0 = *(const ulonglong2*)&Bs[kk][tn*8];
            ulonglong2 B1 = *(const ulonglong2*)&Bs[kk][tn*8 + 4];
            u64 a2[8] = {A0.x, A0.y, A1.x, A1.y, A2.x, A2.y, A3.x, A3.y};
            u64 b2[4] = {B0.x, B0.y, B1.x, B1.y};
            #pragma unroll
            for (int i = 0; i < 8; i++)
                #pragma unroll
                for (int j = 0; j < 4; j++)
                    fma2(acc[i][j], a2[i], b2[j]);
        }
        __syncthreads();
    }
    #pragma unroll
    for (int i = 0; i < 8; i++) {
        int r = row0 + tm*8 + i;
        float bv;
        if (MODE == 0) bv = (r < 192) ? bias0[r] : bias1[r-192];
        else           bv = bias0[r] + bias0[256 + r] + bias0[512 + r];
        float* cp = &Cn[(size_t)r * NCOL + col0 + tn*8];
        #pragma unroll
        for (int j = 0; j < 4; j++) {
            float2 v = up2(acc[i][j]);
            *(float2*)(cp + 2*j) = make_float2(v.x + bv, v.y + bv);
        }
    }
}

// ---------------- K3: scores partials: scores[v,u] = sum_{i,t} fa[i,t,v]*fb[i,t,u]
__global__ void __launch_bounds__(512) k3_scores() {
    __shared__ float sfa[8][320];
    __shared__ float sfb[8][320];
    int tid = threadIdx.x;
    int tc = blockIdx.x;           // 0..15 (16 t values each)
    int ns = blockIdx.y;           // n*3+s
    int n = ns / 3, s = ns % 3;
    const float* faB = g_fab + (size_t)n*M1*NCOL + (size_t)(s*64)*NCOL + tc*320;
    const float* fbB = faB + (size_t)192*NCOL;
    float acc = 0.f;
    int v = tid / 20, u = tid % 20;
    for (int ib = 0; ib < 64; ib += 8) {
        for (int idx = tid; idx < 2560; idx += 512) {
            int ii = idx / 320, jj = idx % 320;
            sfa[ii][jj] = faB[(size_t)(ib+ii)*NCOL + jj];
            sfb[ii][jj] = fbB[(size_t)(ib+ii)*NCOL + jj];
        }
        __syncthreads();
        if (tid < 400) {
            #pragma unroll
            for (int ii = 0; ii < 8; ii++)
                #pragma unroll
                for (int t = 0; t < 16; t++)
                    acc += sfa[ii][t*20 + v] * sfb[ii][t*20 + u];
        }
        __syncthreads();
    }
    if (tid < 400)
        g_spart[(tc*48 + ns)*400 + tid] = acc * (1.0f/16384.0f);
}

// ---------------- K4: reduce partials, softmax over v (axis -2), + (A_fix+PA) --
__global__ void __launch_bounds__(512) k4_softmax(const float* __restrict__ PA,
                                                  const float* __restrict__ A_fix) {
    __shared__ float ssc[400];
    int tid = threadIdx.x;
    int ns = blockIdx.x;
    int s = ns % 3;
    if (tid < 400) {
        float a = 0.f;
        #pragma unroll
        for (int tc = 0; tc < 16; tc++) a += g_spart[(tc*48 + ns)*400 + tid];
        ssc[tid] = a;
    }
    __syncthreads();
    if (tid < 20) {
        int u = tid;
        float mx = -1e30f;
        #pragma unroll
        for (int v = 0; v < 20; v++) mx = fmaxf(mx, ssc[v*20 + u]);
        float e[20];
        float sum = 0.f;
        #pragma unroll
        for (int v = 0; v < 20; v++) { e[v] = expf(ssc[v*20 + u] - mx); sum += e[v]; }
        float inv = 1.0f / sum;
        #pragma unroll
        for (int v = 0; v < 20; v++) {
            int ai = (s*20 + v)*20 + u;
            g_att[ns*400 + v*20 + u] = e[v]*inv + A_fix[ai] + PA[ai];
        }
    }
}

// ---------------- K5: z[n,s,row,:] = xp[n,row,:] @ att[n,s] for ALL s ---------
__global__ void __launch_bounds__(256) k5_z() {
    __shared__ float satt[3*400];
    int tid = threadIdx.x;
    int n = blockIdx.y;
    for (int i = tid; i < 3*400; i += 256) satt[i] = g_att[n*1200 + i];
    __syncthreads();
    size_t row = (size_t)blockIdx.x * 256 + tid;   // grid.x = 256 -> 65536 rows
    const float* xr0 = &g_xp[((size_t)n*CT + row)*VPN];
    float xr[20];
    #pragma unroll
    for (int q = 0; q < 5; q++)
        *(float4*)&xr[q*4] = *(const float4*)(xr0 + q*4);
    #pragma unroll
    for (int s = 0; s < 3; s++) {
        float acc[20];
        #pragma unroll
        for (int u = 0; u < 20; u++) acc[u] = 0.f;
        #pragma unroll
        for (int v = 0; v < 20; v++) {
            float x0 = xr[v];
            #pragma unroll
            for (int u = 0; u < 20; u++)
                acc[u] += x0 * satt[s*400 + v*20 + u];
        }
        float* zp = &g_z[(((size_t)n*3 + s)*CT + row)*VPN];
        #pragma unroll
        for (int q = 0; q < 5; q++)
            *(float4*)(zp + q*4) = make_float4(acc[q*4], acc[q*4+1], acc[q*4+2], acc[q*4+3]);
    }
}

// ---------------- K7: BN statistics (training mode, biased var) ---------------
__global__ void __launch_bounds__(256) k7_bn() {
    __shared__ double ssum[256];
    __shared__ double ssq[256];
    int o = blockIdx.x, tid = threadIdx.x;
    double s = 0.0, q = 0.0;
    for (int n = 0; n < NB; n++) {
        const float* yp = &g_y[((size_t)n*CCH + o)*NCOL];
        for (int j = tid; j < NCOL; j += 256) { double v = yp[j]; s += v; q += v*v; }
    }
    ssum[tid] = s; ssq[tid] = q;
    __syncthreads();
    for (int st = 128; st > 0; st >>= 1) {
        if (tid < st) { ssum[tid] += ssum[tid+st]; ssq[tid] += ssq[tid+st]; }
        __syncthreads();
    }
    if (tid == 0) {
        double cnt  = (double)NB * NCOL;
        double mean = ssum[0] / cnt;
        double var  = ssq[0] / cnt - mean*mean;
        g_bn[o]       = (float)mean;
        g_bn[256 + o] = (float)(1.0 / sqrt(var + 1e-5));
    }
}

// ---------------- K8: out = relu(BN(y)*gamma+beta + xp) -----------------------
__global__ void __launch_bounds__(256) k8_final(const float* __restrict__ gamma,
                                                const float* __restrict__ beta,
                                                float* __restrict__ out) {
    size_t idx = ((size_t)blockIdx.x * 256 + threadIdx.x) * 4;
    int o = (int)((idx / NCOL) % CCH);
    float rstd = g_bn[256 + o];
    float g = gamma[o] * rstd;
    float b = beta[o] - g_bn[o] * g;
    float4 y  = *(const float4*)&g_y[idx];
    float4 xp = *(const float4*)&g_xp[idx];
    float4 r;
    r.x = fmaxf(y.x*g + b + xp.x, 0.f);
    r.y = fmaxf(y.y*g + b + xp.y, 0.f);
    r.z = fmaxf(y.z*g + b + xp.z, 0.f);
    r.w = fmaxf(y.w*g + b + xp.w, 0.f);
    *(float4*)&out[idx] = r;
}

// ---------------- launch --------------------------------------------------------
extern "C" void kernel_launch(void* const* d_in, const int* in_sizes, int n_in,
                              void* d_out, int out_size) {
    const float* x     = (const float*)d_in[0];
    const float* PA    = (const float*)d_in[1];
    const float* A_fix = (const float*)d_in[2];
    const float* w_e   = (const float*)d_in[3];
    const float* b_e   = (const float*)d_in[4];
    const float* wa    = (const float*)d_in[5];
    const float* ba    = (const float*)d_in[6];
    const float* wb    = (const float*)d_in[7];
    const float* bb    = (const float*)d_in[8];
    const float* wd    = (const float*)d_in[9];
    const float* bd    = (const float*)d_in[10];
    const float* gamma = (const float*)d_in[11];
    const float* beta  = (const float*)d_in[12];
    float* out = (float*)d_out;

    k1_xp<<<2048, 256>>>(x, w_e, b_e);
    gemm_k<0><<<dim3(NCOL/128, M1/128, NB), 256>>>(wa, wb, ba, bb);
    k3_scores<<<dim3(16, 48), 512>>>();
    k4_softmax<<<48, 512>>>(PA, A_fix);
    k5_z<<<dim3(256, 16), 256>>>();
    gemm_k<1><<<dim3(NCOL/128, M2/128, NB), 256>>>(wd, nullptr, bd, nullptr);
    k7_bn<<<CCH, 256>>>();
    k8_final<<<20480, 256>>>(gamma, beta, out);
}

// round 5
// speedup vs baseline: 1.2035x; 1.2035x over previous
#include <cuda_runtime.h>

// Problem dims
#define NB  16
#define CCH 256
#define TT  256
#define VV  25
#define VPN 20
#define SS  3
#define ICN 64
#define CT   (CCH*TT)      // 65536
#define NCOL (TT*VPN)      // 5120
#define M1 384             // fa|fb stacked rows
#define KK1 256
#define M2 256
#define KK2 768

// ---------------- scratch (device globals; no runtime allocation) -------------
__device__ float g_xp[(size_t)NB*CT*VPN];        // (N, C*T, VP)
__device__ float g_fab[(size_t)NB*M1*NCOL];      // (N, 384, 5120)
__device__ float g_spart[16*48*400];             // score partials per t-chunk
__device__ float g_att[48*400];                  // (N*S, VP, VP)
__device__ float g_z[(size_t)NB*SS*CT*VPN];      // (N,S,C*T,VP)
__device__ float g_y[(size_t)NB*CCH*NCOL];       // (N, C, T*VP)
__device__ float g_bn[2*CCH];                    // mean, rstd

// ---------------- packed fp32x2 helpers ----------------
typedef unsigned long long u64;
__device__ __forceinline__ u64 dup2(float x){ u64 r; asm("mov.b64 %0, {%1,%1};" : "=l"(r) : "f"(x)); return r; }
__device__ __forceinline__ void fma2(u64 &d, u64 a, u64 b){ asm("fma.rn.f32x2 %0, %1, %2, %0;" : "+l"(d) : "l"(a), "l"(b)); }
__device__ __forceinline__ float2 up2(u64 v){ float lo, hi; asm("mov.b64 {%0,%1}, %2;" : "=f"(lo), "=f"(hi) : "l"(v)); return make_float2(lo,hi); }

// ---------------- K1: xp = einsum('nctv,vu->nctu', x, w_e) + b_e --------------
__global__ void __launch_bounds__(256) k1_xp(const float* __restrict__ x,
                                             const float* __restrict__ w_e,
                                             const float* __restrict__ b_e) {
    __shared__ float sw[VV*VPN];
    __shared__ float sb[VPN];
    int tid = threadIdx.x;
    for (int i = tid; i < VV*VPN; i += 256) sw[i] = w_e[i];
    if (tid < VPN) sb[tid] = b_e[tid];
    __syncthreads();
    size_t row0 = ((size_t)blockIdx.x * 256 + tid) * 2;
    float xr[2][VV];
    #pragma unroll
    for (int r = 0; r < 2; r++) {
        const float* xr0 = x + (row0 + r) * VV;
        #pragma unroll
        for (int v = 0; v < VV; v++) xr[r][v] = xr0[v];
    }
    float acc[2][VPN];
    #pragma unroll
    for (int u = 0; u < VPN; u++) { float b = sb[u]; acc[0][u] = b; acc[1][u] = b; }
    #pragma unroll
    for (int v = 0; v < VV; v++) {
        float x0 = xr[0][v], x1 = xr[1][v];
        #pragma unroll
        for (int u = 0; u < VPN; u++) {
            float w = sw[v*VPN + u];
            acc[0][u] += x0 * w;
            acc[1][u] += x1 * w;
        }
    }
    #pragma unroll
    for (int r = 0; r < 2; r++) {
        float* o = &g_xp[(row0 + r) * VPN];
        #pragma unroll
        for (int q = 0; q < 5; q++)
            *(float4*)(o + q*4) = make_float4(acc[r][q*4], acc[r][q*4+1], acc[r][q*4+2], acc[r][q*4+3]);
    }
}

// ---------------- tiled batched GEMM (128x128x16, 8x8 micro, f32x2) -----------
// Non-duplicated A (4 LDS.128/thread/kk keeps crossbar at the FFMA2 floor),
// B loaded directly as packed u64 pairs (no MOV), A broadcast via dup2 MOVs.
// __launch_bounds__(256,2) caps regs at 128 -> 2 CTAs/SM (16 warps, latency
// hiding), no register prefetch so no spills under the cap.
// MODE 0: fa/fb  — A rows: [wa(192x256); wb(192x256)], B = xp[n], C = fab[n]
// MODE 1: y      — A[o][k=s*256+c] = wd[s,o,c],        B = z[n],  C = y[n]
template<int MODE>
__global__ void __launch_bounds__(256, 2) gemm_k(const float* __restrict__ W0,
                                                 const float* __restrict__ W1,
                                                 const float* __restrict__ bias0,
                                                 const float* __restrict__ bias1) {
    constexpr int MM = (MODE == 0) ? M1 : M2;
    constexpr int KD = (MODE == 0) ? KK1 : KK2;
    __shared__ float As[16][132];
    __shared__ float Bs[16][128];

    const float* B    = (MODE == 0) ? g_xp : g_z;
    float*       Cout = (MODE == 0) ? g_fab : g_y;

    int tid = threadIdx.x;
    int n   = blockIdx.z;
    const float* Bn = B    + (size_t)n * KD * NCOL;
    float*       Cn = Cout + (size_t)n * MM * NCOL;

    int row0 = blockIdx.y * 128;
    int col0 = blockIdx.x * 128;
    int tm = tid >> 4, tn = tid & 15;
    int ra = tid >> 2;            // 0..63
    int ka = (tid & 3) << 2;      // 0,4,8,12
    int colb = (tid & 31) << 2;   // 0..124
    int kb = tid >> 5;            // 0..7

    u64 acc[8][4];
    #pragma unroll
    for (int i = 0; i < 8; i++)
        #pragma unroll
        for (int j = 0; j < 4; j++) acc[i][j] = 0ull;

    auto a_ptr = [&](int r, int kg) -> const float* {
        if (MODE == 0) return (r < 192) ? (W0 + r*256 + kg) : (W1 + (r-192)*256 + kg);
        int s = kg >> 8, c = kg & 255;
        return W0 + s*65536 + r*256 + c;
    };

    for (int k0 = 0; k0 < KD; k0 += 16) {
        #pragma unroll
        for (int h = 0; h < 2; h++) {
            float4 av = *(const float4*)a_ptr(row0 + ra + h*64, k0 + ka);
            As[ka+0][ra + h*64] = av.x;
            As[ka+1][ra + h*64] = av.y;
            As[ka+2][ra + h*64] = av.z;
            As[ka+3][ra + h*64] = av.w;
            *(float4*)&Bs[kb + h*8][colb] =
                *(const float4*)&Bn[(size_t)(k0 + kb + h*8)*NCOL + col0 + colb];
        }
        __syncthreads();
        #pragma unroll
        for (int kk = 0; kk < 16; kk++) {
            float4 a0 = *(const float4*)&As[kk][tm*8];
            float4 a1 = *(const float4*)&As[kk][tm*8 + 4];
            ulonglong2 B0 = *(const ulonglong2*)&Bs[kk][tn*8];
            ulonglong2 B1 = *(const ulonglong2*)&Bs[kk][tn*8 + 4];
            u64 a2[8];
            a2[0]=dup2(a0.x); a2[1]=dup2(a0.y); a2[2]=dup2(a0.z); a2[3]=dup2(a0.w);
            a2[4]=dup2(a1.x); a2[5]=dup2(a1.y); a2[6]=dup2(a1.z); a2[7]=dup2(a1.w);
            u64 b2[4] = {B0.x, B0.y, B1.x, B1.y};
            #pragma unroll
            for (int i = 0; i < 8; i++)
                #pragma unroll
                for (int j = 0; j < 4; j++)
                    fma2(acc[i][j], a2[i], b2[j]);
        }
        __syncthreads();
    }
    #pragma unroll
    for (int i = 0; i < 8; i++) {
        int r = row0 + tm*8 + i;
        float bv;
        if (MODE == 0) bv = (r < 192) ? bias0[r] : bias1[r-192];
        else           bv = bias0[r] + bias0[256 + r] + bias0[512 + r];
        float* cp = &Cn[(size_t)r * NCOL + col0 + tn*8];
        #pragma unroll
        for (int j = 0; j < 4; j++) {
            float2 v = up2(acc[i][j]);
            *(float2*)(cp + 2*j) = make_float2(v.x + bv, v.y + bv);
        }
    }
}

// ---------------- K3: scores partials: scores[v,u] = sum_{i,t} fa[i,t,v]*fb[i,t,u]
__global__ void __launch_bounds__(512) k3_scores() {
    __shared__ float sfa[8][320];
    __shared__ float sfb[8][320];
    int tid = threadIdx.x;
    int tc = blockIdx.x;           // 0..15 (16 t values each)
    int ns = blockIdx.y;           // n*3+s
    int n = ns / 3, s = ns % 3;
    const float* faB = g_fab + (size_t)n*M1*NCOL + (size_t)(s*64)*NCOL + tc*320;
    const float* fbB = faB + (size_t)192*NCOL;
    float acc = 0.f;
    int v = tid / 20, u = tid % 20;
    for (int ib = 0; ib < 64; ib += 8) {
        for (int idx = tid; idx < 2560; idx += 512) {
            int ii = idx / 320, jj = idx % 320;
            sfa[ii][jj] = faB[(size_t)(ib+ii)*NCOL + jj];
            sfb[ii][jj] = fbB[(size_t)(ib+ii)*NCOL + jj];
        }
        __syncthreads();
        if (tid < 400) {
            #pragma unroll
            for (int ii = 0; ii < 8; ii++)
                #pragma unroll
                for (int t = 0; t < 16; t++)
                    acc += sfa[ii][t*20 + v] * sfb[ii][t*20 + u];
        }
        __syncthreads();
    }
    if (tid < 400)
        g_spart[(tc*48 + ns)*400 + tid] = acc * (1.0f/16384.0f);
}

// ---------------- K4: reduce partials, softmax over v (axis -2), + (A_fix+PA) --
__global__ void __launch_bounds__(512) k4_softmax(const float* __restrict__ PA,
                                                  const float* __restrict__ A_fix) {
    __shared__ float ssc[400];
    int tid = threadIdx.x;
    int ns = blockIdx.x;
    int s = ns % 3;
    if (tid < 400) {
        float a = 0.f;
        #pragma unroll
        for (int tc = 0; tc < 16; tc++) a += g_spart[(tc*48 + ns)*400 + tid];
        ssc[tid] = a;
    }
    __syncthreads();
    if (tid < 20) {
        int u = tid;
        float mx = -1e30f;
        #pragma unroll
        for (int v = 0; v < 20; v++) mx = fmaxf(mx, ssc[v*20 + u]);
        float e[20];
        float sum = 0.f;
        #pragma unroll
        for (int v = 0; v < 20; v++) { e[v] = expf(ssc[v*20 + u] - mx); sum += e[v]; }
        float inv = 1.0f / sum;
        #pragma unroll
        for (int v = 0; v < 20; v++) {
            int ai = (s*20 + v)*20 + u;
            g_att[ns*400 + v*20 + u] = e[v]*inv + A_fix[ai] + PA[ai];
        }
    }
}

// ---------------- K5: z[n,s,row,:] = xp[n,row,:] @ att[n,s] for ALL s ---------
__global__ void __launch_bounds__(256) k5_z() {
    __shared__ float satt[3*400];
    int tid = threadIdx.x;
    int n = blockIdx.y;
    for (int i = tid; i < 3*400; i += 256) satt[i] = g_att[n*1200 + i];
    __syncthreads();
    size_t row = (size_t)blockIdx.x * 256 + tid;   // grid.x = 256 -> 65536 rows
    const float* xr0 = &g_xp[((size_t)n*CT + row)*VPN];
    float xr[20];
    #pragma unroll
    for (int q = 0; q < 5; q++)
        *(float4*)&xr[q*4] = *(const float4*)(xr0 + q*4);
    #pragma unroll
    for (int s = 0; s < 3; s++) {
        float acc[20];
        #pragma unroll
        for (int u = 0; u < 20; u++) acc[u] = 0.f;
        #pragma unroll
        for (int v = 0; v < 20; v++) {
            float x0 = xr[v];
            #pragma unroll
            for (int u = 0; u < 20; u++)
                acc[u] += x0 * satt[s*400 + v*20 + u];
        }
        float* zp = &g_z[(((size_t)n*3 + s)*CT + row)*VPN];
        #pragma unroll
        for (int q = 0; q < 5; q++)
            *(float4*)(zp + q*4) = make_float4(acc[q*4], acc[q*4+1], acc[q*4+2], acc[q*4+3]);
    }
}

// ---------------- K7: BN statistics (training mode, biased var) ---------------
__global__ void __launch_bounds__(256) k7_bn() {
    __shared__ double ssum[256];
    __shared__ double ssq[256];
    int o = blockIdx.x, tid = threadIdx.x;
    double s = 0.0, q = 0.0;
    for (int n = 0; n < NB; n++) {
        const float* yp = &g_y[((size_t)n*CCH + o)*NCOL];
        for (int j = tid; j < NCOL; j += 256) { double v = yp[j]; s += v; q += v*v; }
    }
    ssum[tid] = s; ssq[tid] = q;
    __syncthreads();
    for (int st = 128; st > 0; st >>= 1) {
        if (tid < st) { ssum[tid] += ssum[tid+st]; ssq[tid] += ssq[tid+st]; }
        __syncthreads();
    }
    if (tid == 0) {
        double cnt  = (double)NB * NCOL;
        double mean = ssum[0] / cnt;
        double var  = ssq[0] / cnt - mean*mean;
        g_bn[o]       = (float)mean;
        g_bn[256 + o] = (float)(1.0 / sqrt(var + 1e-5));
    }
}

// ---------------- K8: out = relu(BN(y)*gamma+beta + xp) -----------------------
__global__ void __launch_bounds__(256) k8_final(const float* __restrict__ gamma,
                                                const float* __restrict__ beta,
                                                float* __restrict__ out) {
    size_t idx = ((size_t)blockIdx.x * 256 + threadIdx.x) * 4;
    int o = (int)((idx / NCOL) % CCH);
    float rstd = g_bn[256 + o];
    float g = gamma[o] * rstd;
    float b = beta[o] - g_bn[o] * g;
    float4 y  = *(const float4*)&g_y[idx];
    float4 xp = *(const float4*)&g_xp[idx];
    float4 r;
    r.x = fmaxf(y.x*g + b + xp.x, 0.f);
    r.y = fmaxf(y.y*g + b + xp.y, 0.f);
    r.z = fmaxf(y.z*g + b + xp.z, 0.f);
    r.w = fmaxf(y.w*g + b + xp.w, 0.f);
    *(float4*)&out[idx] = r;
}

// ---------------- launch --------------------------------------------------------
extern "C" void kernel_launch(void* const* d_in, const int* in_sizes, int n_in,
                              void* d_out, int out_size) {
    const float* x     = (const float*)d_in[0];
    const float* PA    = (const float*)d_in[1];
    const float* A_fix = (const float*)d_in[2];
    const float* w_e   = (const float*)d_in[3];
    const float* b_e   = (const float*)d_in[4];
    const float* wa    = (const float*)d_in[5];
    const float* ba    = (const float*)d_in[6];
    const float* wb    = (const float*)d_in[7];
    const float* bb    = (const float*)d_in[8];
    const float* wd    = (const float*)d_in[9];
    const float* bd    = (const float*)d_in[10];
    const float* gamma = (const float*)d_in[11];
    const float* beta  = (const float*)d_in[12];
    float* out = (float*)d_out;

    k1_xp<<<2048, 256>>>(x, w_e, b_e);
    gemm_k<0><<<dim3(NCOL/128, M1/128, NB), 256>>>(wa, wb, ba, bb);
    k3_scores<<<dim3(16, 48), 512>>>();
    k4_softmax<<<48, 512>>>(PA, A_fix);
    k5_z<<<dim3(256, 16), 256>>>();
    gemm_k<1><<<dim3(NCOL/128, M2/128, NB), 256>>>(wd, nullptr, bd, nullptr);
    k7_bn<<<CCH, 256>>>();
    k8_final<<<20480, 256>>>(gamma, beta, out);
}

// round 7
// speedup vs baseline: 1.8400x; 1.5290x over previous
#include <cuda_runtime.h>
#include <cuda_bf16.h>
#include <cstdint>

// Problem dims
#define NB  16
#define CCH 256
#define TT  256
#define VV  25
#define VPN 20
#define SS  3
#define ICN 64
#define CT   (CCH*TT)      // 65536
#define NCOL (TT*VPN)      // 5120
#define M1 384
#define KK1 256
#define M2 256
#define KK2 768

// ---------------- scratch (device globals; no runtime allocation) -------------
__device__ float g_xp[(size_t)NB*CT*VPN];
__device__ float g_fab[(size_t)NB*M1*NCOL];
__device__ float g_spart[16*48*400];
__device__ float g_att[48*400];
__device__ float g_z[(size_t)NB*SS*CT*VPN];
__device__ float g_y[(size_t)NB*CCH*NCOL];
__device__ float g_bn[2*CCH];
// pre-split bf16 weight images, laid out exactly as the smem tiles:
// per chunk: [split hi|lo][128 rows][40 bf16 (32 k + 8 pad)]  = 10240 elems
__device__ __nv_bfloat16 g_w0[3*8*10240];    // GEMM0: 3 rowTiles x 8 chunks
__device__ __nv_bfloat16 g_w1[2*24*10240];   // GEMM1: 2 rowTiles x 24 chunks

// ---------------- weight prep: fp32 -> split bf16 images -----------------------
__global__ void prep_w0(const float* __restrict__ wa, const float* __restrict__ wb) {
    int r = blockIdx.x;          // 0..383
    int k = threadIdx.x;         // 0..255
    float v = (r < 192) ? wa[r*256 + k] : wb[(r-192)*256 + k];
    __nv_bfloat16 h = __float2bfloat16(v);
    __nv_bfloat16 l = __float2bfloat16(v - __bfloat162float(h));
    int rowTile = r >> 7, m = r & 127, ch = k >> 5, kk = k & 31;
    size_t base = (size_t)(rowTile*8 + ch) * 10240;
    g_w0[base +        m*40 + kk] = h;
    g_w0[base + 5120 + m*40 + kk] = l;
}
__global__ void prep_w1(const float* __restrict__ wd) {
    int r = blockIdx.x;          // 0..255 (output channel o)
    int k = threadIdx.x;         // 0..767 (s*256 + c)
    float v = wd[(k >> 8)*65536 + r*256 + (k & 255)];
    __nv_bfloat16 h = __float2bfloat16(v);
    __nv_bfloat16 l = __float2bfloat16(v - __bfloat162float(h));
    int rowTile = r >> 7, m = r & 127, ch = k >> 5, kk = k & 31;
    size_t base = (size_t)(rowTile*24 + ch) * 10240;
    g_w1[base +        m*40 + kk] = h;
    g_w1[base + 5120 + m*40 + kk] = l;
}

// ---------------- K1: xp = einsum('nctv,vu->nctu', x, w_e) + b_e --------------
__global__ void __launch_bounds__(256) k1_xp(const float* __restrict__ x,
                                             const float* __restrict__ w_e,
                                             const float* __restrict__ b_e) {
    __shared__ float sw[VV*VPN];
    __shared__ float sb[VPN];
    int tid = threadIdx.x;
    for (int i = tid; i < VV*VPN; i += 256) sw[i] = w_e[i];
    if (tid < VPN) sb[tid] = b_e[tid];
    __syncthreads();
    size_t row0 = ((size_t)blockIdx.x * 256 + tid) * 2;
    float xr[2][VV];
    #pragma unroll
    for (int r = 0; r < 2; r++) {
        const float* xr0 = x + (row0 + r) * VV;
        #pragma unroll
        for (int v = 0; v < VV; v++) xr[r][v] = xr0[v];
    }
    float acc[2][VPN];
    #pragma unroll
    for (int u = 0; u < VPN; u++) { float b = sb[u]; acc[0][u] = b; acc[1][u] = b; }
    #pragma unroll
    for (int v = 0; v < VV; v++) {
        float x0 = xr[0][v], x1 = xr[1][v];
        #pragma unroll
        for (int u = 0; u < VPN; u++) {
            float w = sw[v*VPN + u];
            acc[0][u] += x0 * w;
            acc[1][u] += x1 * w;
        }
    }
    #pragma unroll
    for (int r = 0; r < 2; r++) {
        float* o = &g_xp[(row0 + r) * VPN];
        #pragma unroll
        for (int q = 0; q < 5; q++)
            *(float4*)(o + q*4) = make_float4(acc[r][q*4], acc[r][q*4+1], acc[r][q*4+2], acc[r][q*4+3]);
    }
}

// ---------------- HMMA GEMM: mma.sync m16n8k16 bf16, split hi/lo, fp32 acc ----
// D[r][col] = sum_k W[r][k] * act[k][col]; A = weights (M side), B = act (N side)
// MODE 0: W = wa|wb (384 rows, K=256), act = xp, out = fab
// MODE 1: W = wd-merged (256 rows, K=768), act = z, out = y
__device__ __forceinline__ void mma_bf16(float* c, const uint32_t* a, const uint32_t* b) {
    asm volatile(
        "mma.sync.aligned.m16n8k16.row.col.f32.bf16.bf16.f32 "
        "{%0,%1,%2,%3}, {%4,%5,%6,%7}, {%8,%9}, {%0,%1,%2,%3};"
        : "+f"(c[0]), "+f"(c[1]), "+f"(c[2]), "+f"(c[3])
        : "r"(a[0]), "r"(a[1]), "r"(a[2]), "r"(a[3]), "r"(b[0]), "r"(b[1]));
}

template<int MODE>
__global__ void __launch_bounds__(256) gemm_mma(const float* __restrict__ bias0,
                                                const float* __restrict__ bias1) {
    constexpr int NCH = MODE ? 24 : 8;
    __shared__ __align__(16) __nv_bfloat16 sA[2][128][40];
    __shared__ __align__(16) __nv_bfloat16 sB[2][128][40];

    const __nv_bfloat16* img = MODE ? g_w1 : g_w0;
    const float* act = MODE ? g_z : g_xp;

    int tid = threadIdx.x, lane = tid & 31, wid = tid >> 5;
    int g = lane >> 2, t = lane & 3;
    int col0 = blockIdx.x * 128;
    int rowTile = blockIdx.y;
    int n = blockIdx.z;
    size_t actBase = (size_t)n * (MODE ? 3932160 : 1310720) + col0;
    int Mw = (wid & 3) * 32, Nw = (wid >> 2) * 64;

    float acc[2][8][4];
    #pragma unroll
    for (int i = 0; i < 2; i++)
        #pragma unroll
        for (int j = 0; j < 8; j++)
            #pragma unroll
            for (int q = 0; q < 4; q++) acc[i][j][q] = 0.f;

    const __nv_bfloat16* wimg = img + (size_t)(rowTile * NCH) * 10240;
    int cS = tid & 127, kbS = tid >> 7;

    for (int ch = 0; ch < NCH; ch++) {
        __syncthreads();
        // stage weights (flat copy of pre-built image)
        {
            const uint4* src = (const uint4*)(wimg + (size_t)ch * 10240);
            uint4* dst = (uint4*)&sA[0][0][0];
            #pragma unroll
            for (int i = 0; i < 5; i++) dst[tid + i*256] = src[tid + i*256];
        }
        // stage activations: fp32 -> split bf16, transposed to [col][k]
        {
            const float* ap = act + actBase + (size_t)(ch*32) * 5120;
            #pragma unroll
            for (int i = 0; i < 16; i++) {
                int kk = kbS + i*2;
                float f = ap[(size_t)kk * 5120 + cS];
                __nv_bfloat16 h = __float2bfloat16(f);
                __nv_bfloat16 l = __float2bfloat16(f - __bfloat162float(h));
                sB[0][cS][kk] = h;
                sB[1][cS][kk] = l;
            }
        }
        __syncthreads();
        #pragma unroll
        for (int k0 = 0; k0 < 32; k0 += 16) {
            uint32_t ah[2][4], al[2][4], bh[8][2], bl[8][2];
            #pragma unroll
            for (int mf = 0; mf < 2; mf++) {
                int r = Mw + mf*16 + g;
                ah[mf][0] = *(const uint32_t*)&sA[0][r  ][k0 + 2*t];
                ah[mf][1] = *(const uint32_t*)&sA[0][r+8][k0 + 2*t];
                ah[mf][2] = *(const uint32_t*)&sA[0][r  ][k0 + 2*t + 8];
                ah[mf][3] = *(const uint32_t*)&sA[0][r+8][k0 + 2*t + 8];
                al[mf][0] = *(const uint32_t*)&sA[1][r  ][k0 + 2*t];
                al[mf][1] = *(const uint32_t*)&sA[1][r+8][k0 + 2*t];
                al[mf][2] = *(const uint32_t*)&sA[1][r  ][k0 + 2*t + 8];
                al[mf][3] = *(const uint32_t*)&sA[1][r+8][k0 + 2*t + 8];
            }
            #pragma unroll
            for (int nf = 0; nf < 8; nf++) {
                int c = Nw + nf*8 + g;
                bh[nf][0] = *(const uint32_t*)&sB[0][c][k0 + 2*t];
                bh[nf][1] = *(const uint32_t*)&sB[0][c][k0 + 2*t + 8];
                bl[nf][0] = *(const uint32_t*)&sB[1][c][k0 + 2*t];
                bl[nf][1] = *(const uint32_t*)&sB[1][c][k0 + 2*t + 8];
            }
            #pragma unroll
            for (int mf = 0; mf < 2; mf++)
                #pragma unroll
                for (int nf = 0; nf < 8; nf++) {
                    mma_bf16(acc[mf][nf], ah[mf], bh[nf]);   // hi*hi
                    mma_bf16(acc[mf][nf], ah[mf], bl[nf]);   // hi*lo
                    mma_bf16(acc[mf][nf], al[mf], bh[nf]);   // lo*hi
                }
        }
    }

    // epilogue: direct global stores (+bias), float2 per c-pair
    float* outb = (MODE ? g_y : g_fab) + (size_t)n * (MODE ? 1310720 : 1966080);
    #pragma unroll
    for (int mf = 0; mf < 2; mf++) {
        int r = rowTile*128 + Mw + mf*16 + g;
        float bv0, bv1;
        if (MODE) {
            bv0 = bias0[r]   + bias0[256 + r]   + bias0[512 + r];
            bv1 = bias0[r+8] + bias0[256 + r+8] + bias0[512 + r+8];
        } else {
            bv0 = (r   < 192) ? bias0[r]   : bias1[r   - 192];
            bv1 = (r+8 < 192) ? bias0[r+8] : bias1[r+8 - 192];
        }
        #pragma unroll
        for (int nf = 0; nf < 8; nf++) {
            int col = col0 + Nw + nf*8 + 2*t;
            float* o = outb + (size_t)r * 5120 + col;
            *(float2*)o              = make_float2(acc[mf][nf][0] + bv0, acc[mf][nf][1] + bv0);
            *(float2*)(o + 8*5120)   = make_float2(acc[mf][nf][2] + bv1, acc[mf][nf][3] + bv1);
        }
    }
}

// ---------------- K3: scores partials ------------------------------------------
__global__ void __launch_bounds__(512) k3_scores() {
    __shared__ float sfa[8][320];
    __shared__ float sfb[8][320];
    int tid = threadIdx.x;
    int tc = blockIdx.x;
    int ns = blockIdx.y;
    int n = ns / 3, s = ns % 3;
    const float* faB = g_fab + (size_t)n*M1*NCOL + (size_t)(s*64)*NCOL + tc*320;
    const float* fbB = faB + (size_t)192*NCOL;
    float acc = 0.f;
    int v = tid / 20, u = tid % 20;
    for (int ib = 0; ib < 64; ib += 8) {
        for (int idx = tid; idx < 2560; idx += 512) {
            int ii = idx / 320, jj = idx % 320;
            sfa[ii][jj] = faB[(size_t)(ib+ii)*NCOL + jj];
            sfb[ii][jj] = fbB[(size_t)(ib+ii)*NCOL + jj];
        }
        __syncthreads();
        if (tid < 400) {
            #pragma unroll
            for (int ii = 0; ii < 8; ii++)
                #pragma unroll
                for (int t2 = 0; t2 < 16; t2++)
                    acc += sfa[ii][t2*20 + v] * sfb[ii][t2*20 + u];
        }
        __syncthreads();
    }
    if (tid < 400)
        g_spart[(tc*48 + ns)*400 + tid] = acc * (1.0f/16384.0f);
}

// ---------------- K4: reduce + softmax over v + (A_fix+PA) ---------------------
__global__ void __launch_bounds__(512) k4_softmax(const float* __restrict__ PA,
                                                  const float* __restrict__ A_fix) {
    __shared__ float ssc[400];
    int tid = threadIdx.x;
    int ns = blockIdx.x;
    int s = ns % 3;
    if (tid < 400) {
        float a = 0.f;
        #pragma unroll
        for (int tc = 0; tc < 16; tc++) a += g_spart[(tc*48 + ns)*400 + tid];
        ssc[tid] = a;
    }
    __syncthreads();
    if (tid < 20) {
        int u = tid;
        float mx = -1e30f;
        #pragma unroll
        for (int v = 0; v < 20; v++) mx = fmaxf(mx, ssc[v*20 + u]);
        float e[20];
        float sum = 0.f;
        #pragma unroll
        for (int v = 0; v < 20; v++) { e[v] = expf(ssc[v*20 + u] - mx); sum += e[v]; }
        float inv = 1.0f / sum;
        #pragma unroll
        for (int v = 0; v < 20; v++) {
            int ai = (s*20 + v)*20 + u;
            g_att[ns*400 + v*20 + u] = e[v]*inv + A_fix[ai] + PA[ai];
        }
    }
}

// ---------------- K5: z for all 3 subsets from one xp read ---------------------
__global__ void __launch_bounds__(256) k5_z() {
    __shared__ float satt[3*400];
    int tid = threadIdx.x;
    int n = blockIdx.y;
    for (int i = tid; i < 3*400; i += 256) satt[i] = g_att[n*1200 + i];
    __syncthreads();
    size_t row = (size_t)blockIdx.x * 256 + tid;
    const float* xr0 = &g_xp[((size_t)n*CT + row)*VPN];
    float xr[20];
    #pragma unroll
    for (int q = 0; q < 5; q++)
        *(float4*)&xr[q*4] = *(const float4*)(xr0 + q*4);
    #pragma unroll
    for (int s = 0; s < 3; s++) {
        float acc[20];
        #pragma unroll
        for (int u = 0; u < 20; u++) acc[u] = 0.f;
        #pragma unroll
        for (int v = 0; v < 20; v++) {
            float x0 = xr[v];
            #pragma unroll
            for (int u = 0; u < 20; u++)
                acc[u] += x0 * satt[s*400 + v*20 + u];
        }
        float* zp = &g_z[(((size_t)n*3 + s)*CT + row)*VPN];
        #pragma unroll
        for (int q = 0; q < 5; q++)
            *(float4*)(zp + q*4) = make_float4(acc[q*4], acc[q*4+1], acc[q*4+2], acc[q*4+3]);
    }
}

// ---------------- K7: BN statistics ---------------------------------------------
__global__ void __launch_bounds__(256) k7_bn() {
    __shared__ double ssum[256];
    __shared__ double ssq[256];
    int o = blockIdx.x, tid = threadIdx.x;
    double s = 0.0, q = 0.0;
    for (int n = 0; n < NB; n++) {
        const float* yp = &g_y[((size_t)n*CCH + o)*NCOL];
        for (int j = tid; j < NCOL; j += 256) { double v = yp[j]; s += v; q += v*v; }
    }
    ssum[tid] = s; ssq[tid] = q;
    __syncthreads();
    for (int st = 128; st > 0; st >>= 1) {
        if (tid < st) { ssum[tid] += ssum[tid+st]; ssq[tid] += ssq[tid+st]; }
        __syncthreads();
    }
    if (tid == 0) {
        double cnt  = (double)NB * NCOL;
        double mean = ssum[0] / cnt;
        double var  = ssq[0] / cnt - mean*mean;
        g_bn[o]       = (float)mean;
        g_bn[256 + o] = (float)(1.0 / sqrt(var + 1e-5));
    }
}

// ---------------- K8: out = relu(BN(y)*gamma+beta + xp) -------------------------
__global__ void __launch_bounds__(256) k8_final(const float* __restrict__ gamma,
                                                const float* __restrict__ beta,
                                                float* __restrict__ out) {
    size_t idx = ((size_t)blockIdx.x * 256 + threadIdx.x) * 4;
    int o = (int)((idx / NCOL) % CCH);
    float rstd = g_bn[256 + o];
    float g = gamma[o] * rstd;
    float b = beta[o] - g_bn[o] * g;
    float4 y  = *(const float4*)&g_y[idx];
    float4 xp = *(const float4*)&g_xp[idx];
    float4 r;
    r.x = fmaxf(y.x*g + b + xp.x, 0.f);
    r.y = fmaxf(y.y*g + b + xp.y, 0.f);
    r.z = fmaxf(y.z*g + b + xp.z, 0.f);
    r.w = fmaxf(y.w*g + b + xp.w, 0.f);
    *(float4*)&out[idx] = r;
}

// ---------------- launch ---------------------------------------------------------
extern "C" void kernel_launch(void* const* d_in, const int* in_sizes, int n_in,
                              void* d_out, int out_size) {
    const float* x     = (const float*)d_in[0];
    const float* PA    = (const float*)d_in[1];
    const float* A_fix = (const float*)d_in[2];
    const float* w_e   = (const float*)d_in[3];
    const float* b_e   = (const float*)d_in[4];
    const float* wa    = (const float*)d_in[5];
    const float* ba    = (const float*)d_in[6];
    const float* wb    = (const float*)d_in[7];
    const float* bb    = (const float*)d_in[8];
    const float* wd    = (const float*)d_in[9];
    const float* bd    = (const float*)d_in[10];
    const float* gamma = (const float*)d_in[11];
    const float* beta  = (const float*)d_in[12];
    float* out = (float*)d_out;

    prep_w0<<<384, 256>>>(wa, wb);
    prep_w1<<<256, 768>>>(wd);
    k1_xp<<<2048, 256>>>(x, w_e, b_e);
    gemm_mma<0><<<dim3(40, 3, 16), 256>>>(ba, bb);
    k3_scores<<<dim3(16, 48), 512>>>();
    k4_softmax<<<48, 512>>>(PA, A_fix);
    k5_z<<<dim3(256, 16), 256>>>();
    gemm_mma<1><<<dim3(40, 2, 16), 256>>>(bd, nullptr);
    k7_bn<<<CCH, 256>>>();
    k8_final<<<20480, 256>>>(gamma, beta, out);
}